// round 1
// baseline (speedup 1.0000x reference)
#include <cuda_runtime.h>
#include <math.h>

#define Bq 4
#define Nq 512
#define DIN 128
#define F 64
#define NN (Nq*Nq)        // 262144
#define ALPHA 0.2f
#define ROWS_PER_BLK 8

// scratch (no allocations allowed)
__device__ float g_h[Bq*Nq*F];
__device__ float g_s1[Bq*Nq];
__device__ float g_t[Bq*Nq];

// ---------------------------------------------------------------------------
// Kernel A: h = x@W + b ; s1 = h.a1 ; t = h.a2   (one block per (b,n) row)
// ---------------------------------------------------------------------------
__global__ __launch_bounds__(64) void gat_h_kernel(
    const float* __restrict__ x, const float* __restrict__ W,
    const float* __restrict__ bias, const float* __restrict__ a)
{
    int row = blockIdx.x;            // b*Nq + n
    int f   = threadIdx.x;           // 0..63
    __shared__ float xs[DIN];
    __shared__ float rs[2][2];

    xs[f]      = x[row*DIN + f];
    xs[f + 64] = x[row*DIN + 64 + f];
    __syncthreads();

    float acc = bias[f];
#pragma unroll 8
    for (int k = 0; k < DIN; ++k)
        acc += xs[k] * W[k*F + f];

    g_h[row*F + f] = acc;

    float v1 = acc * a[f];
    float v2 = acc * a[64 + f];
    int lane = f & 31, warp = f >> 5;
#pragma unroll
    for (int o = 16; o; o >>= 1) {
        v1 += __shfl_xor_sync(0xffffffffu, v1, o);
        v2 += __shfl_xor_sync(0xffffffffu, v2, o);
    }
    if (lane == 0) { rs[warp][0] = v1; rs[warp][1] = v2; }
    __syncthreads();
    if (f == 0) {
        g_s1[row] = rs[0][0] + rs[1][0];
        g_t [row] = rs[0][1] + rs[1][1];
    }
}

// ---------------------------------------------------------------------------
// Kernel B: per block, 8 rows of one batch: logits -> masked softmax -> AV -> elu
// 256 threads. smem: s1/t tables (4KB) + probs[8][512] (16KB, reused for reduce)
// ---------------------------------------------------------------------------
__global__ __launch_bounds__(256) void gat_attn_kernel(
    const int* __restrict__ adj, float* __restrict__ out)
{
    __shared__ float s1s[Nq];
    __shared__ float ts [Nq];
    __shared__ float probs[ROWS_PER_BLK][Nq];   // logits -> probs -> acc-reduce scratch
    __shared__ float denom[ROWS_PER_BLK];

    int tid = threadIdx.x;
    int b   = blockIdx.x >> 6;                  // 64 row-blocks per batch
    int n0  = (blockIdx.x & 63) << 3;

    // ---- load score tables ----
    for (int i = tid; i < Nq; i += 256) {
        s1s[i] = g_s1[b*Nq + i];
        ts [i] = g_t [b*Nq + i];
    }
    __syncthreads();

    // ---- phase 1: masked leaky-relu logits for 8 rows ----
    const int* adjb = adj + (long)b*Nq*Nq;
    for (int i = tid; i < ROWS_PER_BLK*Nq; i += 256) {
        int r = i >> 9;
        int m = i & (Nq-1);
        int n = n0 + r;
        int q1 = 2*(n*Nq + m);
        int q2 = q1 + 1;
        int idx1 = (q1 < NN) ? (q1 >> 9) : ((q1 - NN) & (Nq-1));
        int idx2 = (q2 < NN) ? (q2 >> 9) : ((q2 - NN) & (Nq-1));
        float e = s1s[idx1] + ts[idx2];
        e = (e > 0.0f) ? e : ALPHA*e;
        int ad = adjb[n*Nq + m];
        probs[r][m] = (ad > 0) ? e : -1e30f;
    }
    __syncthreads();

    // ---- phase 2: per-row softmax (one warp per row) ----
    int lane = tid & 31;
    int wid  = tid >> 5;                         // 0..7 = row
    {
        float mx = -1e30f;
        for (int m = lane; m < Nq; m += 32) mx = fmaxf(mx, probs[wid][m]);
#pragma unroll
        for (int o = 16; o; o >>= 1) mx = fmaxf(mx, __shfl_xor_sync(0xffffffffu, mx, o));
        float sum = 0.0f;
        for (int m = lane; m < Nq; m += 32) {
            float p = __expf(probs[wid][m] - mx);
            probs[wid][m] = p;
            sum += p;
        }
#pragma unroll
        for (int o = 16; o; o >>= 1) sum += __shfl_xor_sync(0xffffffffu, sum, o);
        if (lane == 0) denom[wid] = sum;
    }
    __syncthreads();

    // ---- phase 3: AV. thread = (f-pair, m-group); each h element feeds 8 rows ----
    int f2 = tid & 31;                           // float2 column 0..31
    int g  = tid >> 5;                           // m-group 0..7
    float2 acc[ROWS_PER_BLK];
#pragma unroll
    for (int r = 0; r < ROWS_PER_BLK; ++r) acc[r] = make_float2(0.f, 0.f);

    const float2* h2 = (const float2*)(g_h + (long)b*Nq*F);
    for (int m = g; m < Nq; m += 8) {
        float2 hv = h2[m*32 + f2];
#pragma unroll
        for (int r = 0; r < ROWS_PER_BLK; ++r) {
            float p = probs[r][m];
            acc[r].x += p * hv.x;
            acc[r].y += p * hv.y;
        }
    }
    __syncthreads();                             // probs no longer needed

    // ---- reduce over 8 m-groups, finalize ----
    float2* red = (float2*)&probs[0][0];         // 8g * 8r * 32f2 float2 = 16KB, fits
#pragma unroll
    for (int r = 0; r < ROWS_PER_BLK; ++r)
        red[((g*8) + r)*32 + f2] = acc[r];
    __syncthreads();

    // thread -> (row = wid, f-pair = lane)
    float2 o = make_float2(0.f, 0.f);
#pragma unroll
    for (int gg = 0; gg < 8; ++gg) {
        float2 v = red[((gg*8) + wid)*32 + lane];
        o.x += v.x; o.y += v.y;
    }
    float inv = 1.0f / denom[wid];
    o.x *= inv; o.y *= inv;
    o.x = (o.x > 0.0f) ? o.x : expm1f(o.x);
    o.y = (o.y > 0.0f) ? o.y : expm1f(o.y);
    ((float2*)out)[((long)(b*Nq) + n0 + wid)*32 + lane] = o;
}

// ---------------------------------------------------------------------------
extern "C" void kernel_launch(void* const* d_in, const int* in_sizes, int n_in,
                              void* d_out, int out_size)
{
    const float* x    = (const float*)d_in[0];
    const int*   adj  = (const int*)  d_in[1];
    const float* W    = (const float*)d_in[2];
    const float* bias = (const float*)d_in[3];
    const float* a    = (const float*)d_in[4];
    float* out = (float*)d_out;

    gat_h_kernel<<<Bq*Nq, 64>>>(x, W, bias, a);
    gat_attn_kernel<<<(Bq*Nq)/ROWS_PER_BLK, 256>>>(adj, out);
}

// round 2
// speedup vs baseline: 1.0732x; 1.0732x over previous
#include <cuda_runtime.h>
#include <math.h>

#define Bq 4
#define Nq 512
#define DIN 128
#define F 64
#define NN (Nq*Nq)        // 262144
#define ALPHA 0.2f
#define ROWS 8
#define THREADS 512

// scratch (no allocations allowed)
__device__ float g_h[Bq*Nq*F];
__device__ float g_s1[Bq*Nq];
__device__ float g_t[Bq*Nq];

// ---------------------------------------------------------------------------
// Kernel A: tiled  h = x@W + b ; s1 = h.a1 ; t = h.a2
// 16 rows per block, 256 threads. W staged in smem once per block.
// thread: f2 = tid&31 (float2 feature pair), rq = tid>>5 (row pair 0..7)
// ---------------------------------------------------------------------------
__global__ __launch_bounds__(256) void gat_h_kernel(
    const float* __restrict__ x, const float* __restrict__ W,
    const float* __restrict__ bias, const float* __restrict__ a)
{
    __shared__ float xs[16*DIN];       // 8KB
    __shared__ float Ws[DIN*F];        // 32KB

    int tid  = threadIdx.x;
    int row0 = blockIdx.x * 16;        // global row = b*Nq + n

    // cooperative loads (float4)
    {
        const float4* xsrc = (const float4*)(x + (long)row0*DIN);
        float4* xdst = (float4*)xs;
        #pragma unroll
        for (int i = 0; i < 2; ++i)
            xdst[tid + 256*i] = xsrc[tid + 256*i];
        const float4* wsrc = (const float4*)W;
        float4* wdst = (float4*)Ws;
        #pragma unroll
        for (int i = 0; i < 8; ++i)
            wdst[tid + 256*i] = wsrc[tid + 256*i];
    }
    __syncthreads();

    int f2 = tid & 31;                 // float2 feature index 0..31
    int rq = tid >> 5;                 // row pair 0..7 (= warp id)
    int r0 = rq*2, r1 = rq*2 + 1;

    float2 bv = ((const float2*)bias)[f2];
    float2 acc0 = bv, acc1 = bv;

    const float2* Ws2 = (const float2*)Ws;
    #pragma unroll 8
    for (int k = 0; k < DIN; ++k) {
        float2 w = Ws2[k*32 + f2];
        float x0 = xs[r0*DIN + k];
        float x1 = xs[r1*DIN + k];
        acc0.x += x0*w.x; acc0.y += x0*w.y;
        acc1.x += x1*w.x; acc1.y += x1*w.y;
    }

    // store h
    float2* h2 = (float2*)g_h;
    h2[(long)(row0 + r0)*32 + f2] = acc0;
    h2[(long)(row0 + r1)*32 + f2] = acc1;

    // s1 / t : full row lives in one warp (f2 spans all 64 features)
    float2 a1 = ((const float2*)a)[f2];
    float2 a2 = ((const float2*)a)[32 + f2];
    float s1_0 = acc0.x*a1.x + acc0.y*a1.y;
    float s1_1 = acc1.x*a1.x + acc1.y*a1.y;
    float t_0  = acc0.x*a2.x + acc0.y*a2.y;
    float t_1  = acc1.x*a2.x + acc1.y*a2.y;
    #pragma unroll
    for (int o = 16; o; o >>= 1) {
        s1_0 += __shfl_xor_sync(0xffffffffu, s1_0, o);
        s1_1 += __shfl_xor_sync(0xffffffffu, s1_1, o);
        t_0  += __shfl_xor_sync(0xffffffffu, t_0,  o);
        t_1  += __shfl_xor_sync(0xffffffffu, t_1,  o);
    }
    if (f2 == 0) {
        g_s1[row0 + r0] = s1_0;
        g_s1[row0 + r1] = s1_1;
        g_t [row0 + r0] = t_0;
        g_t [row0 + r1] = t_1;
    }
}

// ---------------------------------------------------------------------------
// Kernel B: 8 rows per block, 512 threads (16 warps), grid 256.
// ---------------------------------------------------------------------------
__global__ __launch_bounds__(THREADS, 2) void gat_attn_kernel(
    const int* __restrict__ adj, float* __restrict__ out)
{
    __shared__ float s1s[Nq];
    __shared__ float ts [Nq];
    __shared__ float buf[8192];            // probs[8][512] (16KB) -> red (32KB)
    __shared__ float pmax[ROWS][2];
    __shared__ float psum[ROWS][2];

    int tid = threadIdx.x;
    int b   = blockIdx.x >> 6;
    int n0  = (blockIdx.x & 63) << 3;
    float (*probs)[Nq] = (float(*)[Nq])buf;

    for (int i = tid; i < Nq; i += THREADS) {
        s1s[i] = g_s1[b*Nq + i];
        ts [i] = g_t [b*Nq + i];
    }
    __syncthreads();

    // ---- phase 1: masked leaky-relu logits (adj via int4) ----
    {
        int r  = tid >> 6;                 // row 0..7
        int m0 = (tid & 63) << 3;          // 8 consecutive m
        int n  = n0 + r;
        const int4* ap = (const int4*)(adj + ((long)b*Nq + n)*Nq + m0);
        int4 a0 = ap[0], a1 = ap[1];
        int av[8] = {a0.x,a0.y,a0.z,a0.w,a1.x,a1.y,a1.z,a1.w};
        #pragma unroll
        for (int j = 0; j < 8; ++j) {
            int m  = m0 + j;
            int q1 = 2*(n*Nq + m);
            int idx1 = (q1   < NN) ? (q1   >> 9) : ((q1   - NN) & (Nq-1));
            int idx2 = (q1+1 < NN) ? ((q1+1)>> 9) : ((q1+1 - NN) & (Nq-1));
            float e = s1s[idx1] + ts[idx2];
            e = (e > 0.0f) ? e : ALPHA*e;
            probs[r][m] = (av[j] > 0) ? e : -1e30f;
        }
    }
    __syncthreads();

    // ---- phase 2: softmax, 2 warps per row ----
    int lane = tid & 31;
    int wid  = tid >> 5;                   // 0..15
    {
        int r  = wid & 7;
        int hf = wid >> 3;
        int mb = hf << 8;                  // 0 or 256
        float mx = -1e30f;
        for (int m = mb + lane; m < mb + 256; m += 32)
            mx = fmaxf(mx, probs[r][m]);
        #pragma unroll
        for (int o = 16; o; o >>= 1) mx = fmaxf(mx, __shfl_xor_sync(0xffffffffu, mx, o));
        if (lane == 0) pmax[r][hf] = mx;
        __syncthreads();
        mx = fmaxf(pmax[r][0], pmax[r][1]);
        float sum = 0.0f;
        for (int m = mb + lane; m < mb + 256; m += 32) {
            float p = __expf(probs[r][m] - mx);
            probs[r][m] = p;
            sum += p;
        }
        #pragma unroll
        for (int o = 16; o; o >>= 1) sum += __shfl_xor_sync(0xffffffffu, sum, o);
        if (lane == 0) psum[r][hf] = sum;
    }
    __syncthreads();

    // ---- phase 3: AV, 16 m-groups, acc[8] in regs ----
    int f2 = lane;                         // float2 feature 0..31
    int g  = wid;                          // m-group 0..15
    float2 acc[ROWS];
    #pragma unroll
    for (int r = 0; r < ROWS; ++r) acc[r] = make_float2(0.f, 0.f);

    const float2* h2 = (const float2*)(g_h + (long)b*Nq*F);
    #pragma unroll 4
    for (int k = 0; k < 32; ++k) {
        int m = g + (k << 4);
        float2 hv = h2[m*32 + f2];
        #pragma unroll
        for (int r = 0; r < ROWS; ++r) {
            float p = probs[r][m];
            acc[r].x += p * hv.x;
            acc[r].y += p * hv.y;
        }
    }
    __syncthreads();                       // probs dead, reuse buf as red

    float2* red = (float2*)buf;            // [16 g][8 r][32 f2] float2 = 32KB
    #pragma unroll
    for (int r = 0; r < ROWS; ++r)
        red[(g*ROWS + r)*32 + f2] = acc[r];
    __syncthreads();

    if (tid < 256) {
        int r = tid >> 5;                  // 0..7
        float2 o = make_float2(0.f, 0.f);
        #pragma unroll
        for (int gg = 0; gg < 16; ++gg) {
            float2 v = red[(gg*ROWS + r)*32 + f2];
            o.x += v.x; o.y += v.y;
        }
        float inv = 1.0f / (psum[r][0] + psum[r][1]);
        o.x *= inv; o.y *= inv;
        o.x = (o.x > 0.0f) ? o.x : expm1f(o.x);
        o.y = (o.y > 0.0f) ? o.y : expm1f(o.y);
        ((float2*)out)[((long)(b*Nq) + n0 + r)*32 + f2] = o;
    }
}

// ---------------------------------------------------------------------------
extern "C" void kernel_launch(void* const* d_in, const int* in_sizes, int n_in,
                              void* d_out, int out_size)
{
    const float* x    = (const float*)d_in[0];
    const int*   adj  = (const int*)  d_in[1];
    const float* W    = (const float*)d_in[2];
    const float* bias = (const float*)d_in[3];
    const float* a    = (const float*)d_in[4];
    float* out = (float*)d_out;

    gat_h_kernel<<<(Bq*Nq)/16, 256>>>(x, W, bias, a);
    gat_attn_kernel<<<(Bq*Nq)/ROWS, THREADS>>>(adj, out);
}

// round 4
// speedup vs baseline: 1.0867x; 1.0126x over previous
#include <cuda_runtime.h>
#include <math.h>

#define Bq 4
#define Nq 512
#define DIN 128
#define F 64
#define NN (Nq*Nq)
#define ALPHA 0.2f
#define MSPLIT 4
#define MCHUNK (Nq/MSPLIT)     // 128

// scratch
__device__ float g_h[Bq*Nq*F];
__device__ float g_s1[Bq*Nq];
__device__ float g_t[Bq*Nq];
__device__ float g_part[MSPLIT*Bq*Nq*F];   // 2MB partial AV
__device__ float g_psum[MSPLIT*Bq*Nq];     // partial row sums

// ---------------------------------------------------------------------------
// Kernel A: h = x@W + b ; s1 = h.a1 ; t = h.a2. Warp per row, grid 256.
// ---------------------------------------------------------------------------
__global__ __launch_bounds__(256) void gat_h_kernel(
    const float* __restrict__ x, const float* __restrict__ W,
    const float* __restrict__ bias, const float* __restrict__ a)
{
    int tid  = threadIdx.x;
    int f2   = tid & 31;
    int row  = blockIdx.x*8 + (tid >> 5);

    const float2* W2 = (const float2*)W;
    const float*  xr = x + (long)row*DIN;

    float2 acc = ((const float2*)bias)[f2];
    #pragma unroll 8
    for (int k = 0; k < DIN; ++k) {
        float xk = __ldg(xr + k);
        float2 w = W2[k*32 + f2];
        acc.x += xk*w.x; acc.y += xk*w.y;
    }
    ((float2*)g_h)[(long)row*32 + f2] = acc;

    float2 a1 = ((const float2*)a)[f2];
    float2 a2 = ((const float2*)a)[32 + f2];
    float s1 = acc.x*a1.x + acc.y*a1.y;
    float t  = acc.x*a2.x + acc.y*a2.y;
    #pragma unroll
    for (int o = 16; o; o >>= 1) {
        s1 += __shfl_xor_sync(0xffffffffu, s1, o);
        t  += __shfl_xor_sync(0xffffffffu, t,  o);
    }
    if (f2 == 0) { g_s1[row] = s1; g_t[row] = t; }
}

// ---------------------------------------------------------------------------
// Kernel B: 8 rows x 128-m chunk per block. 256 threads, grid 1024.
// Fused: masked exp(leakyrelu(logits)) + partial sums + partial AV.
// ---------------------------------------------------------------------------
__global__ __launch_bounds__(256) void gat_attn_kernel(const int* __restrict__ adj)
{
    __shared__ float s1s[Nq];
    __shared__ float ts [Nq];
    __shared__ __align__(16) float buf[4096];   // probs[8][128] (4KB) then red (16KB)
    float (*probs)[MCHUNK] = (float(*)[MCHUNK])buf;

    int tid  = threadIdx.x;
    int lane = tid & 31;
    int wid  = tid >> 5;                 // 0..7
    int bid  = blockIdx.x;
    int ms   = bid & 3;
    int rb   = (bid >> 2) & 63;
    int b    = bid >> 8;
    int n0   = rb << 3;
    int m0   = ms * MCHUNK;

    for (int i = tid; i < Nq; i += 256) {
        s1s[i] = g_s1[b*Nq + i];
        ts [i] = g_t [b*Nq + i];
    }
    __syncthreads();

    // ---- phase 1: exp(leakyrelu(logits)) masked, + row partial sums ----
    {
        int n  = n0 + wid;
        int ma = m0 + lane*4;            // absolute m, 4 per thread
        const int4 av = *(const int4*)(adj + ((long)b*Nq + n)*Nq + ma);
        int avv[4] = {av.x, av.y, av.z, av.w};
        float4 p4;
        float* pp = (float*)&p4;
        float sum = 0.f;
        #pragma unroll
        for (int j = 0; j < 4; ++j) {
            int m  = ma + j;
            int q1 = 2*(n*Nq + m);
            int idx1 = (q1   < NN) ? (q1   >> 9) : ((q1   - NN) & (Nq-1));
            int idx2 = (q1+1 < NN) ? ((q1+1)>> 9) : ((q1+1 - NN) & (Nq-1));
            float e = s1s[idx1] + ts[idx2];
            e = (e > 0.0f) ? e : ALPHA*e;
            float p = (avv[j] > 0) ? __expf(e) : 0.0f;
            pp[j] = p; sum += p;
        }
        *(float4*)&probs[wid][lane*4] = p4;
        #pragma unroll
        for (int o = 16; o; o >>= 1) sum += __shfl_xor_sync(0xffffffffu, sum, o);
        if (lane == 0) g_psum[(ms*Bq + b)*Nq + n] = sum;
    }
    __syncthreads();

    // ---- phase 2: partial AV. warp = 16 contiguous m, lane = f2 ----
    float2 acc[8];
    #pragma unroll
    for (int r = 0; r < 8; ++r) acc[r] = make_float2(0.f, 0.f);

    const float2* h2 = (const float2*)(g_h + (long)b*Nq*F);
    #pragma unroll
    for (int kc = 0; kc < 4; ++kc) {
        int mloc = wid*16 + kc*4;
        int mabs = m0 + mloc;
        float2 hv0 = h2[(mabs+0)*32 + lane];
        float2 hv1 = h2[(mabs+1)*32 + lane];
        float2 hv2 = h2[(mabs+2)*32 + lane];
        float2 hv3 = h2[(mabs+3)*32 + lane];
        #pragma unroll
        for (int r = 0; r < 8; ++r) {
            float4 p = *(const float4*)&probs[r][mloc];
            acc[r].x += p.x*hv0.x + p.y*hv1.x + p.z*hv2.x + p.w*hv3.x;
            acc[r].y += p.x*hv0.y + p.y*hv1.y + p.z*hv2.y + p.w*hv3.y;
        }
    }
    __syncthreads();                      // probs dead; buf becomes red (16KB)

    float2* red = (float2*)buf;           // [8 g][8 r][32 f2]
    #pragma unroll
    for (int r = 0; r < 8; ++r)
        red[(wid*8 + r)*32 + lane] = acc[r];
    __syncthreads();

    // reduce over 8 groups, store partial
    {
        int r = wid;
        float2 o = make_float2(0.f, 0.f);
        #pragma unroll
        for (int g = 0; g < 8; ++g) {
            float2 v = red[(g*8 + r)*32 + lane];
            o.x += v.x; o.y += v.y;
        }
        ((float2*)g_part)[((long)(ms*Bq + b)*Nq + n0 + r)*32 + lane] = o;
    }
}

// ---------------------------------------------------------------------------
// Kernel C: combine partials, normalize, elu. 256 blocks x 256 thr.
// ---------------------------------------------------------------------------
__global__ __launch_bounds__(256) void gat_combine_kernel(float* __restrict__ out)
{
    int gid = blockIdx.x*256 + threadIdx.x;   // 0..65535
    int row = gid >> 5;                       // b*Nq + n, 0..2047
    int f2  = gid & 31;

    const float2* part2 = (const float2*)g_part;
    float2 o = make_float2(0.f, 0.f);
    float  s = 0.f;
    #pragma unroll
    for (int ms = 0; ms < MSPLIT; ++ms) {
        float2 v = part2[((long)ms*Bq*Nq + row)*32 + f2];
        o.x += v.x; o.y += v.y;
        s += g_psum[ms*Bq*Nq + row];
    }
    float inv = 1.0f / s;
    o.x *= inv; o.y *= inv;
    o.x = (o.x > 0.0f) ? o.x : expm1f(o.x);
    o.y = (o.y > 0.0f) ? o.y : expm1f(o.y);
    ((float2*)out)[(long)row*32 + f2] = o;
}

// ---------------------------------------------------------------------------
extern "C" void kernel_launch(void* const* d_in, const int* in_sizes, int n_in,
                              void* d_out, int out_size)
{
    const float* x    = (const float*)d_in[0];
    const int*   adj  = (const int*)  d_in[1];
    const float* W    = (const float*)d_in[2];
    const float* bias = (const float*)d_in[3];
    const float* a    = (const float*)d_in[4];
    float* out = (float*)d_out;

    gat_h_kernel<<<(Bq*Nq)/8, 256>>>(x, W, bias, a);
    gat_attn_kernel<<<Bq*64*MSPLIT, 256>>>(adj);
    gat_combine_kernel<<<(Bq*Nq*32)/256, 256>>>(out);
}

// round 5
// speedup vs baseline: 1.2047x; 1.1085x over previous
#include <cuda_runtime.h>
#include <math.h>

#define Bq 4
#define Nq 512
#define DIN 128
#define F 64
#define NN (Nq*Nq)
#define ALPHA 0.2f
#define MSPLIT 4
#define MCHUNK (Nq/MSPLIT)     // 128

// scratch
__device__ float g_h[Bq*Nq*F];
__device__ float g_s1[Bq*Nq];
__device__ float g_t[Bq*Nq];
__device__ float g_part[MSPLIT*Bq*Nq*F];   // 2MB partial AV
__device__ float g_psum[MSPLIT*Bq*Nq];     // partial row sums

// ---------------------------------------------------------------------------
// Kernel A: h = x@W + b ; s1 = h.a1 ; t = h.a2.
// 4 rows/block, 2 warps/row (feature halves), grid 512 = 4096 warps.
// x staged in smem; W via L1 (coalesced 128B per warp-iter, L1-resident).
// ---------------------------------------------------------------------------
__global__ __launch_bounds__(256) void gat_h_kernel(
    const float* __restrict__ x, const float* __restrict__ W,
    const float* __restrict__ bias, const float* __restrict__ a)
{
    __shared__ __align__(16) float xs[4*DIN];   // 2KB
    __shared__ float red[4][2][2];              // [row][fhalf][s1|t]

    int tid   = threadIdx.x;
    int lane  = tid & 31;
    int wid   = tid >> 5;          // 0..7
    int rloc  = wid >> 1;          // 0..3
    int fhalf = wid & 1;
    int row0  = blockIdx.x * 4;
    int row   = row0 + rloc;
    int f     = fhalf*32 + lane;

    if (tid < 128)
        ((float4*)xs)[tid] = ((const float4*)(x + (long)row0*DIN))[tid];
    __syncthreads();

    const float* xsr = xs + rloc*DIN;
    float acc = bias[f];
    #pragma unroll 8
    for (int k = 0; k < DIN; ++k)
        acc += xsr[k] * W[k*F + f];

    g_h[(long)row*F + f] = acc;

    float s1p = acc * a[f];
    float tp  = acc * a[F + f];
    #pragma unroll
    for (int o = 16; o; o >>= 1) {
        s1p += __shfl_xor_sync(0xffffffffu, s1p, o);
        tp  += __shfl_xor_sync(0xffffffffu, tp,  o);
    }
    if (lane == 0) { red[rloc][fhalf][0] = s1p; red[rloc][fhalf][1] = tp; }
    __syncthreads();
    if (tid < 4) {
        g_s1[row0 + tid] = red[tid][0][0] + red[tid][1][0];
        g_t [row0 + tid] = red[tid][0][1] + red[tid][1][1];
    }
}

// ---------------------------------------------------------------------------
// Kernel B: 8 rows x 128-m chunk per block. 256 threads, grid 1024.
// Fused: masked exp(leakyrelu(logits)) + partial sums + partial AV.
// ---------------------------------------------------------------------------
__global__ __launch_bounds__(256) void gat_attn_kernel(const int* __restrict__ adj)
{
    __shared__ float s1s[Nq];
    __shared__ float ts [Nq];
    __shared__ __align__(16) float buf[4096];   // probs[8][128] (4KB) then red (16KB)
    float (*probs)[MCHUNK] = (float(*)[MCHUNK])buf;

    int tid  = threadIdx.x;
    int lane = tid & 31;
    int wid  = tid >> 5;                 // 0..7
    int bid  = blockIdx.x;
    int ms   = bid & 3;
    int rb   = (bid >> 2) & 63;
    int b    = bid >> 8;
    int n0   = rb << 3;
    int m0   = ms * MCHUNK;

    for (int i = tid; i < Nq; i += 256) {
        s1s[i] = g_s1[b*Nq + i];
        ts [i] = g_t [b*Nq + i];
    }
    __syncthreads();

    // ---- phase 1: exp(leakyrelu(logits)) masked, + row partial sums ----
    {
        int n  = n0 + wid;
        int ma = m0 + lane*4;            // absolute m, 4 per thread
        const int4 av = *(const int4*)(adj + ((long)b*Nq + n)*Nq + ma);
        int avv[4] = {av.x, av.y, av.z, av.w};
        float4 p4;
        float* pp = (float*)&p4;
        float sum = 0.f;
        #pragma unroll
        for (int j = 0; j < 4; ++j) {
            int m  = ma + j;
            int q1 = 2*(n*Nq + m);
            int idx1 = (q1   < NN) ? (q1   >> 9) : ((q1   - NN) & (Nq-1));
            int idx2 = (q1+1 < NN) ? ((q1+1)>> 9) : ((q1+1 - NN) & (Nq-1));
            float e = s1s[idx1] + ts[idx2];
            e = (e > 0.0f) ? e : ALPHA*e;
            float p = (avv[j] > 0) ? __expf(e) : 0.0f;
            pp[j] = p; sum += p;
        }
        *(float4*)&probs[wid][lane*4] = p4;
        #pragma unroll
        for (int o = 16; o; o >>= 1) sum += __shfl_xor_sync(0xffffffffu, sum, o);
        if (lane == 0) g_psum[(ms*Bq + b)*Nq + n] = sum;
    }
    __syncthreads();

    // ---- phase 2: partial AV. warp = 16 contiguous m, lane = f2 ----
    float2 acc[8];
    #pragma unroll
    for (int r = 0; r < 8; ++r) acc[r] = make_float2(0.f, 0.f);

    const float2* h2 = (const float2*)(g_h + (long)b*Nq*F);
    #pragma unroll
    for (int kc = 0; kc < 4; ++kc) {
        int mloc = wid*16 + kc*4;
        int mabs = m0 + mloc;
        float2 hv0 = h2[(mabs+0)*32 + lane];
        float2 hv1 = h2[(mabs+1)*32 + lane];
        float2 hv2 = h2[(mabs+2)*32 + lane];
        float2 hv3 = h2[(mabs+3)*32 + lane];
        #pragma unroll
        for (int r = 0; r < 8; ++r) {
            float4 p = *(const float4*)&probs[r][mloc];
            acc[r].x += p.x*hv0.x + p.y*hv1.x + p.z*hv2.x + p.w*hv3.x;
            acc[r].y += p.x*hv0.y + p.y*hv1.y + p.z*hv2.y + p.w*hv3.y;
        }
    }
    __syncthreads();                      // probs dead; buf becomes red (16KB)

    float2* red = (float2*)buf;           // [8 g][8 r][32 f2]
    #pragma unroll
    for (int r = 0; r < 8; ++r)
        red[(wid*8 + r)*32 + lane] = acc[r];
    __syncthreads();

    // reduce over 8 groups, store partial
    {
        int r = wid;
        float2 o = make_float2(0.f, 0.f);
        #pragma unroll
        for (int g = 0; g < 8; ++g) {
            float2 v = red[(g*8 + r)*32 + lane];
            o.x += v.x; o.y += v.y;
        }
        ((float2*)g_part)[((long)(ms*Bq + b)*Nq + n0 + r)*32 + lane] = o;
    }
}

// ---------------------------------------------------------------------------
// Kernel C: combine partials, normalize, elu. 256 blocks x 256 thr.
// ---------------------------------------------------------------------------
__global__ __launch_bounds__(256) void gat_combine_kernel(float* __restrict__ out)
{
    int gid = blockIdx.x*256 + threadIdx.x;   // 0..65535
    int row = gid >> 5;                       // b*Nq + n, 0..2047
    int f2  = gid & 31;

    const float2* part2 = (const float2*)g_part;
    float2 o = make_float2(0.f, 0.f);
    float  s = 0.f;
    #pragma unroll
    for (int ms = 0; ms < MSPLIT; ++ms) {
        float2 v = part2[((long)ms*Bq*Nq + row)*32 + f2];
        o.x += v.x; o.y += v.y;
        s += g_psum[ms*Bq*Nq + row];
    }
    float inv = 1.0f / s;
    o.x *= inv; o.y *= inv;
    o.x = (o.x > 0.0f) ? o.x : expm1f(o.x);
    o.y = (o.y > 0.0f) ? o.y : expm1f(o.y);
    ((float2*)out)[(long)row*32 + f2] = o;
}

// ---------------------------------------------------------------------------
extern "C" void kernel_launch(void* const* d_in, const int* in_sizes, int n_in,
                              void* d_out, int out_size)
{
    const float* x    = (const float*)d_in[0];
    const int*   adj  = (const int*)  d_in[1];
    const float* W    = (const float*)d_in[2];
    const float* bias = (const float*)d_in[3];
    const float* a    = (const float*)d_in[4];
    float* out = (float*)d_out;

    gat_h_kernel<<<(Bq*Nq)/4, 256>>>(x, W, bias, a);
    gat_attn_kernel<<<Bq*64*MSPLIT, 256>>>(adj);
    gat_combine_kernel<<<(Bq*Nq*32)/256, 256>>>(out);
}